// round 2
// baseline (speedup 1.0000x reference)
#include <cuda_runtime.h>
#include <math_constants.h>

// KNNRegressor via s(q,c) = |t_c|^2 - 2 q.t_c  (|q|^2 dropped; ordering-invariant).
// Round 2: packed-fp32 FFMA2 (fma.rn.f32x2) GEMM — 2x fp32 FMA throughput.
// k-dimension packed in pairs; accumulator holds partial sums in both halves.
//
// K1: t_sq[c] = |X_train[c]|^2
// K2: fused FFMA2-GEMM (48q x 128c tile, micro 6q x 8c) + streaming warp top-32,
//     candidate dim split 3 ways. 128 thr/CTA, 2 CTAs/SM, grid 86x3=258.
// K3: merge 3*32 candidates/query -> top-32 -> mean(y).

#define DDIM   128
#define QTILE  48
#define CTILE  128
#define SPLITS 3
#define NTHR   128
#define XS     130          // smem row stride (floats) — conflict-free
#define KSEL   32
#define NMAX   100000
#define QMAX   4096

typedef unsigned long long u64;

__device__ float g_tsq [NMAX];
__device__ float g_dist[QMAX * SPLITS * KSEL];
__device__ int   g_idx [QMAX * SPLITS * KSEL];

__device__ __forceinline__ u64 ffma2(u64 a, u64 b, u64 c) {
    u64 d;
    asm("fma.rn.f32x2 %0, %1, %2, %3;" : "=l"(d) : "l"(a), "l"(b), "l"(c));
    return d;
}

// ---------------------------------------------------------------- kernel 1
__global__ void tsq_kernel(const float* __restrict__ X, int n) {
    int row  = blockIdx.x * 8 + (threadIdx.x >> 5);
    int lane = threadIdx.x & 31;
    if (row >= n) return;
    float4 v = reinterpret_cast<const float4*>(X + (size_t)row * DDIM)[lane];
    float s = v.x * v.x + v.y * v.y + v.z * v.z + v.w * v.w;
    #pragma unroll
    for (int o = 16; o; o >>= 1) s += __shfl_xor_sync(0xffffffffu, s, o);
    if (lane == 0) g_tsq[row] = s;
}

// ---------------------------------------------------------------- kernel 2
__global__ void __launch_bounds__(NTHR, 2)
knn_main(const float* __restrict__ Qm, const float* __restrict__ X,
         int n, int q_total) {
    extern __shared__ float smem[];
    float* q_s = smem;                 // [QTILE][XS]
    float* x_s = smem + QTILE * XS;    // [CTILE][XS], reused as score buffer

    const int tid  = threadIdx.x;
    const int lane = tid & 31;
    const int warp = tid >> 5;
    const int TX   = tid & 15;         // candidate group: 8 cands, stride 16
    const int TY   = tid >> 4;         // query group: 6 queries

    const int qbase = blockIdx.x * QTILE;
    const int per   = n / SPLITS;
    const int sbase = blockIdx.y * per;
    const int send  = (blockIdx.y == SPLITS - 1) ? n : sbase + per;

    // Load query tile once ([q][k], row stride XS).
    for (int i = tid; i < QTILE * (DDIM / 2); i += NTHR) {
        int q  = i >> 6;               // 64 float2 per row
        int kg = i & 63;
        int qq = qbase + q; if (qq >= q_total) qq = q_total - 1;
        float2 v = *reinterpret_cast<const float2*>(Qm + (size_t)qq * DDIM + kg * 2);
        *reinterpret_cast<float2*>(q_s + q * XS + kg * 2) = v;
    }

    // Warp-held sorted top-32 per query: warp w owns queries w*12 .. w*12+11.
    float ld[12];
    int   li[12];
    #pragma unroll
    for (int j = 0; j < 12; j++) { ld[j] = CUDART_INF_F; li[j] = 0; }

    for (int cb = sbase; cb < send; cb += CTILE) {
        __syncthreads();               // previous selection done before overwrite
        // Load X chunk [CTILE][DDIM] (zero-fill OOB rows).
        for (int i = tid; i < CTILE * (DDIM / 2); i += NTHR) {
            int c  = i >> 6;
            int kg = i & 63;
            float2 v = make_float2(0.f, 0.f);
            if (cb + c < send)
                v = *reinterpret_cast<const float2*>(X + (size_t)(cb + c) * DDIM + kg * 2);
            *reinterpret_cast<float2*>(x_s + c * XS + kg * 2) = v;
        }
        __syncthreads();

        // 48x128 packed-fp32 GEMM tile; micro-tile 6q x 8c, k in pairs.
        u64 acc[6][8];
        #pragma unroll
        for (int j = 0; j < 6; j++)
            #pragma unroll
            for (int i2 = 0; i2 < 8; i2++) acc[j][i2] = 0ull;

        #pragma unroll 8
        for (int k = 0; k < DDIM; k += 2) {
            u64 a[6], b[8];
            #pragma unroll
            for (int j = 0; j < 6; j++)
                a[j] = *reinterpret_cast<const u64*>(q_s + (TY * 6 + j) * XS + k);
            #pragma unroll
            for (int i2 = 0; i2 < 8; i2++)
                b[i2] = *reinterpret_cast<const u64*>(x_s + (TX + 16 * i2) * XS + k);
            #pragma unroll
            for (int j = 0; j < 6; j++)
                #pragma unroll
                for (int i2 = 0; i2 < 8; i2++)
                    acc[j][i2] = ffma2(a[j], b[i2], acc[j][i2]);
        }
        __syncthreads();

        // Scores: s = tsq[c] - 2*(hi+lo).  OOB -> +inf.
        #pragma unroll
        for (int i2 = 0; i2 < 8; i2++) {
            int c  = TX + 16 * i2;
            bool ok = (cb + c < send);
            float t = ok ? g_tsq[cb + c] : 0.f;
            #pragma unroll
            for (int j = 0; j < 6; j++) {
                int q = TY * 6 + j;
                float2 f = *reinterpret_cast<float2*>(&acc[j][i2]);
                float sc = ok ? fmaf(-2.f, f.x + f.y, t) : CUDART_INF_F;
                x_s[q * CTILE + c] = sc;
            }
        }
        __syncthreads();

        // Streaming top-32 update: warp w owns 12 queries.
        #pragma unroll
        for (int j = 0; j < 12; j++) {
            int q = warp * 12 + j;
            float thr = __shfl_sync(0xffffffffu, ld[j], 31);
            #pragma unroll
            for (int r = 0; r < 4; r++) {
                float val = x_s[q * CTILE + r * 32 + lane];
                unsigned pass = __ballot_sync(0xffffffffu, val < thr);
                while (pass) {
                    int src = __ffs(pass) - 1;
                    pass &= pass - 1;
                    float v  = __shfl_sync(0xffffffffu, val, src);
                    int   gi = cb + r * 32 + src;
                    unsigned m = __ballot_sync(0xffffffffu, v < ld[j]);
                    if (m) {
                        int p = __ffs(m) - 1;
                        float dn = __shfl_up_sync(0xffffffffu, ld[j], 1);
                        int   in = __shfl_up_sync(0xffffffffu, li[j], 1);
                        if (lane > p)       { ld[j] = dn; li[j] = in; }
                        else if (lane == p) { ld[j] = v;  li[j] = gi; }
                    }
                    thr = __shfl_sync(0xffffffffu, ld[j], 31);
                }
            }
        }
    }

    // Emit per-(query, split) sorted top-32.
    #pragma unroll
    for (int j = 0; j < 12; j++) {
        int q = qbase + warp * 12 + j;
        if (q < q_total) {
            int off = (q * SPLITS + blockIdx.y) * KSEL + lane;
            g_dist[off] = ld[j];
            g_idx[off]  = li[j];
        }
    }
}

// ---------------------------------------------------------------- kernel 3
__global__ void knn_merge(const float* __restrict__ y, float* __restrict__ out,
                          int q_total) {
    int q    = blockIdx.x * (blockDim.x >> 5) + (threadIdx.x >> 5);
    int lane = threadIdx.x & 31;
    if (q >= q_total) return;

    float ld = CUDART_INF_F;
    int   li = 0;
    const float* dp = g_dist + (size_t)q * SPLITS * KSEL;
    const int*   ip = g_idx  + (size_t)q * SPLITS * KSEL;

    for (int s = 0; s < SPLITS; s++) {
        float val = dp[s * KSEL + lane];
        int   vi  = ip[s * KSEL + lane];
        float thr = __shfl_sync(0xffffffffu, ld, 31);
        unsigned pass = __ballot_sync(0xffffffffu, val < thr);
        while (pass) {
            int src = __ffs(pass) - 1;
            pass &= pass - 1;
            float v  = __shfl_sync(0xffffffffu, val, src);
            int   gi = __shfl_sync(0xffffffffu, vi,  src);
            unsigned m = __ballot_sync(0xffffffffu, v < ld);
            if (m) {
                int p = __ffs(m) - 1;
                float dn = __shfl_up_sync(0xffffffffu, ld, 1);
                int   in = __shfl_up_sync(0xffffffffu, li, 1);
                if (lane > p)       { ld = dn; li = in; }
                else if (lane == p) { ld = v;  li = gi; }
            }
            thr = __shfl_sync(0xffffffffu, ld, 31);
        }
    }

    float yv = y[li];
    #pragma unroll
    for (int o = 16; o; o >>= 1) yv += __shfl_xor_sync(0xffffffffu, yv, o);
    if (lane == 0) out[q] = yv * (1.0f / (float)KSEL);
}

// ---------------------------------------------------------------- launcher
extern "C" void kernel_launch(void* const* d_in, const int* in_sizes, int n_in,
                              void* d_out, int out_size) {
    const float* Qm = (const float*)d_in[0];
    const float* X  = (const float*)d_in[1];
    const float* y  = (const float*)d_in[2];
    const int q_total = in_sizes[0] / DDIM;   // 4096
    const int n       = in_sizes[2];          // 100000
    float* out = (float*)d_out;

    tsq_kernel<<<(n + 7) / 8, 256>>>(X, n);

    const int smem_bytes = (QTILE + CTILE) * XS * (int)sizeof(float); // 91520
    static int smem_set = 0;
    if (!smem_set) {
        cudaFuncSetAttribute(knn_main, cudaFuncAttributeMaxDynamicSharedMemorySize,
                             smem_bytes);
        smem_set = 1;
    }
    dim3 grid((q_total + QTILE - 1) / QTILE, SPLITS);
    knn_main<<<grid, NTHR, smem_bytes>>>(Qm, X, n, q_total);

    knn_merge<<<(q_total + 7) / 8, 256>>>(y, out, q_total);
}

// round 3
// speedup vs baseline: 1.0023x; 1.0023x over previous
#include <cuda_runtime.h>
#include <math_constants.h>

// KNNRegressor via s(q,c) = |t_c|^2 - 2 q.t_c  (|q|^2 dropped; ordering-invariant).
// Round 2: packed-fp32 FFMA2 (fma.rn.f32x2) GEMM — 2x fp32 FMA throughput.
// k-dimension packed in pairs; accumulator holds partial sums in both halves.
//
// K1: t_sq[c] = |X_train[c]|^2
// K2: fused FFMA2-GEMM (48q x 128c tile, micro 6q x 8c) + streaming warp top-32,
//     candidate dim split 3 ways. 128 thr/CTA, 2 CTAs/SM, grid 86x3=258.
// K3: merge 3*32 candidates/query -> top-32 -> mean(y).

#define DDIM   128
#define QTILE  48
#define CTILE  128
#define SPLITS 3
#define NTHR   128
#define XS     130          // smem row stride (floats) — conflict-free
#define KSEL   32
#define NMAX   100000
#define QMAX   4096

typedef unsigned long long u64;

__device__ float g_tsq [NMAX];
__device__ float g_dist[QMAX * SPLITS * KSEL];
__device__ int   g_idx [QMAX * SPLITS * KSEL];

__device__ __forceinline__ u64 ffma2(u64 a, u64 b, u64 c) {
    u64 d;
    asm("fma.rn.f32x2 %0, %1, %2, %3;" : "=l"(d) : "l"(a), "l"(b), "l"(c));
    return d;
}

// ---------------------------------------------------------------- kernel 1
__global__ void tsq_kernel(const float* __restrict__ X, int n) {
    int row  = blockIdx.x * 8 + (threadIdx.x >> 5);
    int lane = threadIdx.x & 31;
    if (row >= n) return;
    float4 v = reinterpret_cast<const float4*>(X + (size_t)row * DDIM)[lane];
    float s = v.x * v.x + v.y * v.y + v.z * v.z + v.w * v.w;
    #pragma unroll
    for (int o = 16; o; o >>= 1) s += __shfl_xor_sync(0xffffffffu, s, o);
    if (lane == 0) g_tsq[row] = s;
}

// ---------------------------------------------------------------- kernel 2
__global__ void __launch_bounds__(NTHR, 2)
knn_main(const float* __restrict__ Qm, const float* __restrict__ X,
         int n, int q_total) {
    extern __shared__ float smem[];
    float* q_s = smem;                 // [QTILE][XS]
    float* x_s = smem + QTILE * XS;    // [CTILE][XS], reused as score buffer

    const int tid  = threadIdx.x;
    const int lane = tid & 31;
    const int warp = tid >> 5;
    const int TX   = tid & 15;         // candidate group: 8 cands, stride 16
    const int TY   = tid >> 4;         // query group: 6 queries

    const int qbase = blockIdx.x * QTILE;
    const int per   = n / SPLITS;
    const int sbase = blockIdx.y * per;
    const int send  = (blockIdx.y == SPLITS - 1) ? n : sbase + per;

    // Load query tile once ([q][k], row stride XS).
    for (int i = tid; i < QTILE * (DDIM / 2); i += NTHR) {
        int q  = i >> 6;               // 64 float2 per row
        int kg = i & 63;
        int qq = qbase + q; if (qq >= q_total) qq = q_total - 1;
        float2 v = *reinterpret_cast<const float2*>(Qm + (size_t)qq * DDIM + kg * 2);
        *reinterpret_cast<float2*>(q_s + q * XS + kg * 2) = v;
    }

    // Warp-held sorted top-32 per query: warp w owns queries w*12 .. w*12+11.
    float ld[12];
    int   li[12];
    #pragma unroll
    for (int j = 0; j < 12; j++) { ld[j] = CUDART_INF_F; li[j] = 0; }

    for (int cb = sbase; cb < send; cb += CTILE) {
        __syncthreads();               // previous selection done before overwrite
        // Load X chunk [CTILE][DDIM] (zero-fill OOB rows).
        for (int i = tid; i < CTILE * (DDIM / 2); i += NTHR) {
            int c  = i >> 6;
            int kg = i & 63;
            float2 v = make_float2(0.f, 0.f);
            if (cb + c < send)
                v = *reinterpret_cast<const float2*>(X + (size_t)(cb + c) * DDIM + kg * 2);
            *reinterpret_cast<float2*>(x_s + c * XS + kg * 2) = v;
        }
        __syncthreads();

        // 48x128 packed-fp32 GEMM tile; micro-tile 6q x 8c, k in pairs.
        u64 acc[6][8];
        #pragma unroll
        for (int j = 0; j < 6; j++)
            #pragma unroll
            for (int i2 = 0; i2 < 8; i2++) acc[j][i2] = 0ull;

        #pragma unroll 8
        for (int k = 0; k < DDIM; k += 2) {
            u64 a[6], b[8];
            #pragma unroll
            for (int j = 0; j < 6; j++)
                a[j] = *reinterpret_cast<const u64*>(q_s + (TY * 6 + j) * XS + k);
            #pragma unroll
            for (int i2 = 0; i2 < 8; i2++)
                b[i2] = *reinterpret_cast<const u64*>(x_s + (TX + 16 * i2) * XS + k);
            #pragma unroll
            for (int j = 0; j < 6; j++)
                #pragma unroll
                for (int i2 = 0; i2 < 8; i2++)
                    acc[j][i2] = ffma2(a[j], b[i2], acc[j][i2]);
        }
        __syncthreads();

        // Scores: s = tsq[c] - 2*(hi+lo).  OOB -> +inf.
        #pragma unroll
        for (int i2 = 0; i2 < 8; i2++) {
            int c  = TX + 16 * i2;
            bool ok = (cb + c < send);
            float t = ok ? g_tsq[cb + c] : 0.f;
            #pragma unroll
            for (int j = 0; j < 6; j++) {
                int q = TY * 6 + j;
                float2 f = *reinterpret_cast<float2*>(&acc[j][i2]);
                float sc = ok ? fmaf(-2.f, f.x + f.y, t) : CUDART_INF_F;
                x_s[q * CTILE + c] = sc;
            }
        }
        __syncthreads();

        // Streaming top-32 update: warp w owns 12 queries.
        #pragma unroll
        for (int j = 0; j < 12; j++) {
            int q = warp * 12 + j;
            float thr = __shfl_sync(0xffffffffu, ld[j], 31);
            #pragma unroll
            for (int r = 0; r < 4; r++) {
                float val = x_s[q * CTILE + r * 32 + lane];
                unsigned pass = __ballot_sync(0xffffffffu, val < thr);
                while (pass) {
                    int src = __ffs(pass) - 1;
                    pass &= pass - 1;
                    float v  = __shfl_sync(0xffffffffu, val, src);
                    int   gi = cb + r * 32 + src;
                    unsigned m = __ballot_sync(0xffffffffu, v < ld[j]);
                    if (m) {
                        int p = __ffs(m) - 1;
                        float dn = __shfl_up_sync(0xffffffffu, ld[j], 1);
                        int   in = __shfl_up_sync(0xffffffffu, li[j], 1);
                        if (lane > p)       { ld[j] = dn; li[j] = in; }
                        else if (lane == p) { ld[j] = v;  li[j] = gi; }
                    }
                    thr = __shfl_sync(0xffffffffu, ld[j], 31);
                }
            }
        }
    }

    // Emit per-(query, split) sorted top-32.
    #pragma unroll
    for (int j = 0; j < 12; j++) {
        int q = qbase + warp * 12 + j;
        if (q < q_total) {
            int off = (q * SPLITS + blockIdx.y) * KSEL + lane;
            g_dist[off] = ld[j];
            g_idx[off]  = li[j];
        }
    }
}

// ---------------------------------------------------------------- kernel 3
__global__ void knn_merge(const float* __restrict__ y, float* __restrict__ out,
                          int q_total) {
    int q    = blockIdx.x * (blockDim.x >> 5) + (threadIdx.x >> 5);
    int lane = threadIdx.x & 31;
    if (q >= q_total) return;

    float ld = CUDART_INF_F;
    int   li = 0;
    const float* dp = g_dist + (size_t)q * SPLITS * KSEL;
    const int*   ip = g_idx  + (size_t)q * SPLITS * KSEL;

    for (int s = 0; s < SPLITS; s++) {
        float val = dp[s * KSEL + lane];
        int   vi  = ip[s * KSEL + lane];
        float thr = __shfl_sync(0xffffffffu, ld, 31);
        unsigned pass = __ballot_sync(0xffffffffu, val < thr);
        while (pass) {
            int src = __ffs(pass) - 1;
            pass &= pass - 1;
            float v  = __shfl_sync(0xffffffffu, val, src);
            int   gi = __shfl_sync(0xffffffffu, vi,  src);
            unsigned m = __ballot_sync(0xffffffffu, v < ld);
            if (m) {
                int p = __ffs(m) - 1;
                float dn = __shfl_up_sync(0xffffffffu, ld, 1);
                int   in = __shfl_up_sync(0xffffffffu, li, 1);
                if (lane > p)       { ld = dn; li = in; }
                else if (lane == p) { ld = v;  li = gi; }
            }
            thr = __shfl_sync(0xffffffffu, ld, 31);
        }
    }

    float yv = y[li];
    #pragma unroll
    for (int o = 16; o; o >>= 1) yv += __shfl_xor_sync(0xffffffffu, yv, o);
    if (lane == 0) out[q] = yv * (1.0f / (float)KSEL);
}

// ---------------------------------------------------------------- launcher
extern "C" void kernel_launch(void* const* d_in, const int* in_sizes, int n_in,
                              void* d_out, int out_size) {
    const float* Qm = (const float*)d_in[0];
    const float* X  = (const float*)d_in[1];
    const float* y  = (const float*)d_in[2];
    const int q_total = in_sizes[0] / DDIM;   // 4096
    const int n       = in_sizes[2];          // 100000
    float* out = (float*)d_out;

    tsq_kernel<<<(n + 7) / 8, 256>>>(X, n);

    const int smem_bytes = (QTILE + CTILE) * XS * (int)sizeof(float); // 91520
    static int smem_set = 0;
    if (!smem_set) {
        cudaFuncSetAttribute(knn_main, cudaFuncAttributeMaxDynamicSharedMemorySize,
                             smem_bytes);
        smem_set = 1;
    }
    dim3 grid((q_total + QTILE - 1) / QTILE, SPLITS);
    knn_main<<<grid, NTHR, smem_bytes>>>(Qm, X, n, q_total);

    knn_merge<<<(q_total + 7) / 8, 256>>>(y, out, q_total);
}

// round 5
// speedup vs baseline: 1.4862x; 1.4827x over previous
#include <cuda_runtime.h>
#include <cuda_fp16.h>
#include <math_constants.h>
#include <cstdint>

// KNN via s(q,c)=|t|^2-2q.t ; fp16 2-way split (3 passes hh,hl,lh) with
// mma.sync.m16n8k16 (plain sm_103 — tcgen05 is rejected by the harness's
// PTX target). Warp-collective sorted top-32 selection per 32c strip.
#define DDIM      128
#define QTILE     64
#define CTILE     128
#define SPLITS    2
#define NPAD      100352
#define PER_SPLIT (NPAD / SPLITS)      // 50176
#define CHUNKS    (PER_SPLIT / CTILE)  // 392
#define NSTRIP    (SPLITS * 4)         // 8 lists per query
#define KSEL      32
#define QMAX      4096
#define NTHR      256

// smem byte offsets
#define QSTR      136                  // padded row stride in halfs (272B)
#define QS_OFF    0                    // 2 planes * 64 * 136 * 2  = 34816
#define XS_OFF    34816                // 2 bufs * 2 planes * 128*136*2 = 139264
#define XBUF_SZ   69632
#define XPLANE_SZ 34816
#define TSQ_OFF   174080               // 2 slots * 512
#define STAGE_OFF 175104               // 8 warps * 32*33*4 = 33792
#define SM_TOTAL  208896

__device__ __align__(16) __half g_xh[(size_t)NPAD * DDIM];
__device__ __align__(16) __half g_xl[(size_t)NPAD * DDIM];
__device__ __align__(16) float  g_tsq[NPAD];
__device__ float g_dist[QMAX * NSTRIP * KSEL];
__device__ int   g_idx [QMAX * NSTRIP * KSEL];

__device__ __forceinline__ uint32_t smem_u32(const void* p) {
    uint32_t a;
    asm("{ .reg .u64 t; cvta.to.shared.u64 t, %1; cvt.u32.u64 %0, t; }" : "=r"(a) : "l"(p));
    return a;
}
#define CPA16(dst, src) \
    asm volatile("cp.async.cg.shared.global [%0], [%1], 16;" :: "r"(dst), "l"(src))
#define CPA_COMMIT() asm volatile("cp.async.commit_group;" ::: "memory")

__device__ __forceinline__ void ldsm4(uint32_t* r, uint32_t a) {
    asm volatile("ldmatrix.sync.aligned.m8n8.x4.shared.b16 {%0,%1,%2,%3}, [%4];"
                 : "=r"(r[0]), "=r"(r[1]), "=r"(r[2]), "=r"(r[3]) : "r"(a));
}
__device__ __forceinline__ void ldsm2(uint32_t* r, uint32_t a) {
    asm volatile("ldmatrix.sync.aligned.m8n8.x2.shared.b16 {%0,%1}, [%2];"
                 : "=r"(r[0]), "=r"(r[1]) : "r"(a));
}
__device__ __forceinline__ void mma16816(float* d, const uint32_t* a, const uint32_t* b) {
    asm volatile("mma.sync.aligned.m16n8k16.row.col.f32.f16.f16.f32 "
                 "{%0,%1,%2,%3}, {%4,%5,%6,%7}, {%8,%9}, {%0,%1,%2,%3};"
                 : "+f"(d[0]), "+f"(d[1]), "+f"(d[2]), "+f"(d[3])
                 : "r"(a[0]), "r"(a[1]), "r"(a[2]), "r"(a[3]), "r"(b[0]), "r"(b[1]));
}
__device__ __forceinline__ uint32_t pkh(__half a, __half b) {
    __half2 t = __halves2half2(a, b);
    return *reinterpret_cast<uint32_t*>(&t);
}

// ---------------------------------------------------------------- kernel 1
__global__ void split_kernel(const float* __restrict__ X, int n) {
    int row  = blockIdx.x * 8 + (threadIdx.x >> 5);
    int lane = threadIdx.x & 31;
    if (row >= NPAD) return;
    size_t base = (size_t)row * DDIM + lane * 4;
    if (row < n) {
        float4 v = reinterpret_cast<const float4*>(X + (size_t)row * DDIM)[lane];
        float ss = v.x * v.x + v.y * v.y + v.z * v.z + v.w * v.w;
        #pragma unroll
        for (int o = 16; o; o >>= 1) ss += __shfl_xor_sync(0xffffffffu, ss, o);
        if (lane == 0) g_tsq[row] = ss;
        float p[4] = {v.x, v.y, v.z, v.w};
        __half h[4], l[4];
        #pragma unroll
        for (int e = 0; e < 4; e++) {
            h[e] = __float2half_rn(p[e]);
            l[e] = __float2half_rn(p[e] - __half2float(h[e]));
        }
        *reinterpret_cast<uint2*>(g_xh + base) = make_uint2(pkh(h[0], h[1]), pkh(h[2], h[3]));
        *reinterpret_cast<uint2*>(g_xl + base) = make_uint2(pkh(l[0], l[1]), pkh(l[2], l[3]));
    } else {
        if (lane == 0) g_tsq[row] = CUDART_INF_F;
        uint2 z = make_uint2(0u, 0u);
        *reinterpret_cast<uint2*>(g_xh + base) = z;
        *reinterpret_cast<uint2*>(g_xl + base) = z;
    }
}

// ---------------------------------------------------------------- loaders
__device__ __forceinline__ void load_chunk(uint32_t sb, int cb, int buf, int tid) {
    #pragma unroll
    for (int t = 0; t < 16; t++) {
        int idx   = t * NTHR + tid;           // 4096 transfers of 16B
        int plane = idx >> 11;
        int rem   = idx & 2047;
        int row   = rem >> 4;
        int c16   = rem & 15;
        const __half* src = plane ? g_xl : g_xh;
        const char* sp = reinterpret_cast<const char*>(
            src + (size_t)(cb + row) * DDIM) + c16 * 16;
        uint32_t dst = sb + XS_OFF + buf * XBUF_SZ + plane * XPLANE_SZ
                       + (uint32_t)(row * QSTR * 2 + c16 * 16);
        CPA16(dst, sp);
    }
    if (tid < 32) {
        const char* sp = reinterpret_cast<const char*>(g_tsq + cb) + tid * 16;
        CPA16(sb + TSQ_OFF + buf * 512 + tid * 16, sp);
    }
    CPA_COMMIT();
}

// ---------------------------------------------------------------- kernel 2
__global__ void __launch_bounds__(NTHR, 1)
knn_main(const float* __restrict__ Qm, int q_total) {
    extern __shared__ char smem[];
    uint32_t sb = smem_u32(smem);
    const int tid  = threadIdx.x;
    const int lane = tid & 31;
    const int warp = tid >> 5;
    const int wm   = warp >> 2;          // 0..1 : q strip of 32
    const int wn   = warp & 3;           // 0..3 : c strip of 32
    const int split = blockIdx.y;
    const int qbase = blockIdx.x * QTILE;
    const int sbase = split * PER_SPLIT;

    // Prefetch chunk 0 while converting Q.
    load_chunk(sb, sbase, 0, tid);

    // Q (-2x, fp16 hi/lo) -> smem, padded stride.
    __half* qs_h = reinterpret_cast<__half*>(smem + QS_OFF);
    __half* qs_l = qs_h + 64 * QSTR;
    for (int i = tid; i < QTILE * DDIM; i += NTHR) {
        int row = i >> 7, k = i & 127;
        int q = qbase + row; if (q >= q_total) q = q_total - 1;
        float v = -2.f * Qm[(size_t)q * DDIM + k];
        __half h = __float2half_rn(v);
        __half l = __float2half_rn(v - __half2float(h));
        qs_h[row * QSTR + k] = h;
        qs_l[row * QSTR + k] = l;
    }

    float ld[KSEL]; int li[KSEL];
    #pragma unroll
    for (int j = 0; j < KSEL; j++) { ld[j] = CUDART_INF_F; li[j] = 0; }

    // per-lane ldmatrix address offsets (bytes)
    const uint32_t a_off = (uint32_t)((wm * 32 + (lane & 15)) * QSTR + (lane >> 4) * 8) * 2;
    const uint32_t b_off = (uint32_t)((wn * 32 + (lane & 7)) * QSTR + ((lane >> 3) & 1) * 8) * 2;
    float* stg = reinterpret_cast<float*>(smem + STAGE_OFF) + warp * (32 * 33);

    for (int i = 0; i < CHUNKS; i++) {
        const int cur = i & 1, nb = cur ^ 1;
        if (i + 1 < CHUNKS) {
            load_chunk(sb, sbase + (i + 1) * CTILE, nb, tid);
            asm volatile("cp.async.wait_group 1;" ::: "memory");
        } else {
            asm volatile("cp.async.wait_group 0;" ::: "memory");
        }
        __syncthreads();

        float acc[2][4][4];
        #pragma unroll
        for (int mt = 0; mt < 2; mt++)
            #pragma unroll
            for (int nt = 0; nt < 4; nt++)
                #pragma unroll
                for (int e = 0; e < 4; e++) acc[mt][nt][e] = 0.f;

        #pragma unroll 1
        for (int pass = 0; pass < 3; pass++) {
            const int pq = (pass == 2) ? 1 : 0;      // (hh),(hl),(lh)
            const int px = (pass == 1) ? 1 : 0;
            const uint32_t qb = sb + QS_OFF + (uint32_t)pq * (64 * QSTR * 2);
            const uint32_t xb = sb + XS_OFF + cur * XBUF_SZ + px * XPLANE_SZ;
            #pragma unroll
            for (int ks = 0; ks < 8; ks++) {
                uint32_t afr[2][4], bfr[4][2];
                ldsm4(afr[0], qb + a_off + ks * 32);
                ldsm4(afr[1], qb + a_off + 16 * QSTR * 2 + ks * 32);
                #pragma unroll
                for (int nt = 0; nt < 4; nt++)
                    ldsm2(bfr[nt], xb + b_off + nt * 8 * QSTR * 2 + ks * 32);
                #pragma unroll
                for (int mt = 0; mt < 2; mt++)
                    #pragma unroll
                    for (int nt = 0; nt < 4; nt++)
                        mma16816(acc[mt][nt], afr[mt], bfr[nt]);
            }
        }

        // stage scores (32q x 32c per warp)
        #pragma unroll
        for (int mt = 0; mt < 2; mt++)
            #pragma unroll
            for (int nt = 0; nt < 4; nt++)
                #pragma unroll
                for (int e = 0; e < 4; e++) {
                    int r = mt * 16 + (lane >> 2) + (e >> 1) * 8;
                    int c = nt * 8 + (lane & 3) * 2 + (e & 1);
                    stg[r * 33 + c] = acc[mt][nt][e];
                }
        __syncwarp();

        const float myt = reinterpret_cast<const float*>(smem + TSQ_OFF + cur * 512)
                              [wn * 32 + lane];
        const int cbase = sbase + i * CTILE + wn * 32;
        #pragma unroll
        for (int j = 0; j < 32; j++) {
            float val = stg[j * 33 + lane] + myt;
            float thr = __shfl_sync(0xffffffffu, ld[j], 31);
            unsigned pass = __ballot_sync(0xffffffffu, val < thr);
            while (pass) {
                int src = __ffs(pass) - 1;
                pass &= pass - 1;
                float v  = __shfl_sync(0xffffffffu, val, src);
                int   gi = cbase + src;
                unsigned m = __ballot_sync(0xffffffffu, v < ld[j]);
                if (m) {
                    int p = __ffs(m) - 1;
                    float dn = __shfl_up_sync(0xffffffffu, ld[j], 1);
                    int   in = __shfl_up_sync(0xffffffffu, li[j], 1);
                    if (lane > p)       { ld[j] = dn; li[j] = in; }
                    else if (lane == p) { ld[j] = v;  li[j] = gi; }
                    thr = __shfl_sync(0xffffffffu, ld[j], 31);
                }
            }
        }
        __syncthreads();
    }

    // Emit: strip = split*4 + wn, queries qbase + wm*32 + j.
    const int strip = split * 4 + wn;
    #pragma unroll
    for (int j = 0; j < 32; j++) {
        int q = qbase + wm * 32 + j;
        if (q < q_total) {
            int off = (q * NSTRIP + strip) * KSEL + lane;
            g_dist[off] = ld[j];
            g_idx [off] = li[j];
        }
    }
}

// ---------------------------------------------------------------- kernel 3
__global__ void knn_merge(const float* __restrict__ y, float* __restrict__ out,
                          int q_total) {
    int q    = blockIdx.x * (blockDim.x >> 5) + (threadIdx.x >> 5);
    int lane = threadIdx.x & 31;
    if (q >= q_total) return;
    float ld = CUDART_INF_F;
    int   li = 0;
    const float* dp = g_dist + (size_t)q * NSTRIP * KSEL;
    const int*   ip = g_idx  + (size_t)q * NSTRIP * KSEL;
    for (int s = 0; s < NSTRIP; s++) {
        float val = dp[s * KSEL + lane];
        int   vi  = ip[s * KSEL + lane];
        float thr = __shfl_sync(0xffffffffu, ld, 31);
        unsigned pass = __ballot_sync(0xffffffffu, val < thr);
        while (pass) {
            int src = __ffs(pass) - 1;
            pass &= pass - 1;
            float v  = __shfl_sync(0xffffffffu, val, src);
            int   gi = __shfl_sync(0xffffffffu, vi,  src);
            unsigned m = __ballot_sync(0xffffffffu, v < ld);
            if (m) {
                int p = __ffs(m) - 1;
                float dn = __shfl_up_sync(0xffffffffu, ld, 1);
                int   in = __shfl_up_sync(0xffffffffu, li, 1);
                if (lane > p)       { ld = dn; li = in; }
                else if (lane == p) { ld = v;  li = gi; }
                thr = __shfl_sync(0xffffffffu, ld, 31);
            }
        }
    }
    float yv = y[li];
    #pragma unroll
    for (int o = 16; o; o >>= 1) yv += __shfl_xor_sync(0xffffffffu, yv, o);
    if (lane == 0) out[q] = yv * (1.0f / (float)KSEL);
}

// ---------------------------------------------------------------- launcher
extern "C" void kernel_launch(void* const* d_in, const int* in_sizes, int n_in,
                              void* d_out, int out_size) {
    const float* Qm = (const float*)d_in[0];
    const float* X  = (const float*)d_in[1];
    const float* y  = (const float*)d_in[2];
    const int q_total = in_sizes[0] / DDIM;   // 4096
    const int n       = in_sizes[2];          // 100000
    float* out = (float*)d_out;

    split_kernel<<<NPAD / 8, 256>>>(X, n);

    static int smem_set = 0;
    if (!smem_set) {
        cudaFuncSetAttribute(knn_main, cudaFuncAttributeMaxDynamicSharedMemorySize,
                             SM_TOTAL);
        smem_set = 1;
    }
    dim3 grid((q_total + QTILE - 1) / QTILE, SPLITS);
    knn_main<<<grid, NTHR, SM_TOTAL>>>(Qm, q_total);

    knn_merge<<<(q_total + 7) / 8, 256>>>(y, out, q_total);
}

// round 7
// speedup vs baseline: 2.4791x; 1.6681x over previous
#include <cuda_runtime.h>
#include <cuda_fp16.h>
#include <math_constants.h>
#include <cstdint>

// KNN screen-then-refine:
//  K1 split: X -> fp16(x) + tsq (pad rows: 0 / +inf)
//  K2 knn_main: 1-pass fp16 mma screen, approx top-32 indices per (query, strip)
//     (8 strips/query). QTILE=128, CTILE=64, 512 thr, warp tile 16q x 32c.
//  K3 knn_refine: per query, 256 survivors -> exact fp32 distance -> exact
//     top-32 -> mean(y).
#define DDIM      128
#define QTILE     128
#define CTILE     64
#define SPLITS    4
#define NPAD      100352
#define PER_SPLIT (NPAD / SPLITS)      // 25088
#define CHUNKS    (PER_SPLIT / CTILE)  // 392
#define NSTRIP    8                    // 4 splits * 2 c-strips
#define KSEL      32
#define QMAX      4096
#define NTHR      512

#define QSTR      136                  // padded row stride in halfs
#define QS_OFF    0                    // 128*136*2 = 34816
#define XS_OFF    34816                // 2 bufs * 64*136*2 = 34816
#define XBUF_SZ   17408
#define TSQ_OFF   69632                // 2 * 256
#define STAGE_OFF 70144                // 16 warps * 16*33*4 = 33792
#define SM_TOTAL  103936

__device__ __align__(16) __half g_xh[(size_t)NPAD * DDIM];
__device__ __align__(16) float  g_tsq[NPAD];
__device__ int g_idx[QMAX * NSTRIP * KSEL];

__device__ __forceinline__ uint32_t smem_u32(const void* p) {
    uint32_t a;
    asm("{ .reg .u64 t; cvta.to.shared.u64 t, %1; cvt.u32.u64 %0, t; }" : "=r"(a) : "l"(p));
    return a;
}
#define CPA16(dst, src) \
    asm volatile("cp.async.cg.shared.global [%0], [%1], 16;" :: "r"(dst), "l"(src))
#define CPA_COMMIT() asm volatile("cp.async.commit_group;" ::: "memory")

__device__ __forceinline__ void ldsm4(uint32_t* r, uint32_t a) {
    asm volatile("ldmatrix.sync.aligned.m8n8.x4.shared.b16 {%0,%1,%2,%3}, [%4];"
                 : "=r"(r[0]), "=r"(r[1]), "=r"(r[2]), "=r"(r[3]) : "r"(a));
}
__device__ __forceinline__ void mma16816(float* d, const uint32_t* a,
                                         uint32_t b0, uint32_t b1) {
    asm volatile("mma.sync.aligned.m16n8k16.row.col.f32.f16.f16.f32 "
                 "{%0,%1,%2,%3}, {%4,%5,%6,%7}, {%8,%9}, {%0,%1,%2,%3};"
                 : "+f"(d[0]), "+f"(d[1]), "+f"(d[2]), "+f"(d[3])
                 : "r"(a[0]), "r"(a[1]), "r"(a[2]), "r"(a[3]), "r"(b0), "r"(b1));
}
__device__ __forceinline__ uint32_t pkh(__half a, __half b) {
    __half2 t = __halves2half2(a, b);
    return *reinterpret_cast<uint32_t*>(&t);
}

// ---------------------------------------------------------------- kernel 1
__global__ void split_kernel(const float* __restrict__ X, int n) {
    int row  = blockIdx.x * 8 + (threadIdx.x >> 5);
    int lane = threadIdx.x & 31;
    if (row >= NPAD) return;
    size_t base = (size_t)row * DDIM + lane * 4;
    if (row < n) {
        float4 v = reinterpret_cast<const float4*>(X + (size_t)row * DDIM)[lane];
        float ss = v.x * v.x + v.y * v.y + v.z * v.z + v.w * v.w;
        #pragma unroll
        for (int o = 16; o; o >>= 1) ss += __shfl_xor_sync(0xffffffffu, ss, o);
        if (lane == 0) g_tsq[row] = ss;
        *reinterpret_cast<uint2*>(g_xh + base) =
            make_uint2(pkh(__float2half_rn(v.x), __float2half_rn(v.y)),
                       pkh(__float2half_rn(v.z), __float2half_rn(v.w)));
    } else {
        if (lane == 0) g_tsq[row] = CUDART_INF_F;
        *reinterpret_cast<uint2*>(g_xh + base) = make_uint2(0u, 0u);
    }
}

// ---------------------------------------------------------------- loader
// 64 rows * 256B/row = 1024 x 16B transfers -> 2 per thread (FIXED: round 6
// only loaded the first 128B of each row).
__device__ __forceinline__ void load_chunk(uint32_t sb, int cb, int buf, int tid) {
    #pragma unroll
    for (int t = 0; t < 2; t++) {
        int idx = t * NTHR + tid;
        int row = idx >> 4, c16 = idx & 15;
        const char* sp = reinterpret_cast<const char*>(
            g_xh + (size_t)(cb + row) * DDIM) + c16 * 16;
        CPA16(sb + XS_OFF + buf * XBUF_SZ + (uint32_t)(row * QSTR * 2 + c16 * 16), sp);
    }
    if (tid < 16) {
        const char* tp = reinterpret_cast<const char*>(g_tsq + cb) + tid * 16;
        CPA16(sb + TSQ_OFF + buf * 256 + tid * 16, tp);
    }
    CPA_COMMIT();
}

// ---------------------------------------------------------------- kernel 2
__global__ void __launch_bounds__(NTHR, 1)
knn_main(const float* __restrict__ Qm, int q_total) {
    extern __shared__ char smem[];
    uint32_t sb = smem_u32(smem);
    const int tid  = threadIdx.x;
    const int lane = tid & 31;
    const int warp = tid >> 5;
    const int wm   = warp >> 1;          // 0..7 : q strip of 16
    const int wn   = warp & 1;           // 0..1 : c strip of 32
    const int split = blockIdx.y;
    const int qbase = blockIdx.x * QTILE;
    const int sbase = split * PER_SPLIT;

    load_chunk(sb, sbase, 0, tid);

    // Q (-2x, fp16) -> smem
    __half* qs = reinterpret_cast<__half*>(smem + QS_OFF);
    for (int i = tid; i < QTILE * DDIM; i += NTHR) {
        int row = i >> 7, k = i & 127;
        int q = qbase + row; if (q >= q_total) q = q_total - 1;
        qs[row * QSTR + k] = __float2half_rn(-2.f * Qm[(size_t)q * DDIM + k]);
    }

    float ld[16]; int li[16];
    #pragma unroll
    for (int j = 0; j < 16; j++) { ld[j] = CUDART_INF_F; li[j] = 0; }

    const uint32_t a_off = sb + QS_OFF
        + (uint32_t)((wm * 16 + (lane & 15)) * QSTR + (lane >> 4) * 8) * 2;
    const uint32_t b_off0 = (uint32_t)((wn * 32 + (lane & 15)) * QSTR + (lane >> 4) * 8) * 2;
    const uint32_t b_off1 = b_off0 + (uint32_t)(16 * QSTR * 2);
    float* stg = reinterpret_cast<float*>(smem + STAGE_OFF) + warp * (16 * 33);

    for (int i = 0; i < CHUNKS; i++) {
        const int cur = i & 1, nb = cur ^ 1;
        if (i + 1 < CHUNKS) {
            load_chunk(sb, sbase + (i + 1) * CTILE, nb, tid);
            asm volatile("cp.async.wait_group 1;" ::: "memory");
        } else {
            asm volatile("cp.async.wait_group 0;" ::: "memory");
        }
        __syncthreads();

        float acc[4][4];
        #pragma unroll
        for (int nt = 0; nt < 4; nt++)
            #pragma unroll
            for (int e = 0; e < 4; e++) acc[nt][e] = 0.f;

        const uint32_t xb = sb + XS_OFF + cur * XBUF_SZ;
        #pragma unroll
        for (int ks = 0; ks < 8; ks++) {
            uint32_t af[4], b0[4], b1[4];
            ldsm4(af, a_off + ks * 32);
            ldsm4(b0, xb + b_off0 + ks * 32);
            ldsm4(b1, xb + b_off1 + ks * 32);
            mma16816(acc[0], af, b0[0], b0[2]);
            mma16816(acc[1], af, b0[1], b0[3]);
            mma16816(acc[2], af, b1[0], b1[2]);
            mma16816(acc[3], af, b1[1], b1[3]);
        }

        // stage 16q x 32c scores
        #pragma unroll
        for (int nt = 0; nt < 4; nt++)
            #pragma unroll
            for (int e = 0; e < 4; e++) {
                int r = (lane >> 2) + (e >> 1) * 8;
                int c = nt * 8 + (lane & 3) * 2 + (e & 1);
                stg[r * 33 + c] = acc[nt][e];
            }
        __syncwarp();

        const float myt = reinterpret_cast<const float*>(smem + TSQ_OFF + cur * 256)
                              [wn * 32 + lane];
        const int cbase = sbase + i * CTILE + wn * 32;
        #pragma unroll
        for (int j = 0; j < 16; j++) {
            float val = stg[j * 33 + lane] + myt;
            float thr = __shfl_sync(0xffffffffu, ld[j], 31);
            unsigned pass = __ballot_sync(0xffffffffu, val < thr);
            while (pass) {
                int src = __ffs(pass) - 1;
                pass &= pass - 1;
                float v  = __shfl_sync(0xffffffffu, val, src);
                int   gi = cbase + src;
                unsigned m = __ballot_sync(0xffffffffu, v < ld[j]);
                if (m) {
                    int p = __ffs(m) - 1;
                    float dn = __shfl_up_sync(0xffffffffu, ld[j], 1);
                    int   in = __shfl_up_sync(0xffffffffu, li[j], 1);
                    if (lane > p)       { ld[j] = dn; li[j] = in; }
                    else if (lane == p) { ld[j] = v;  li[j] = gi; }
                    thr = __shfl_sync(0xffffffffu, ld[j], 31);
                }
            }
        }
        __syncthreads();
    }

    const int strip = split * 2 + wn;
    #pragma unroll
    for (int j = 0; j < 16; j++) {
        int q = qbase + wm * 16 + j;
        if (q < q_total)
            g_idx[(q * NSTRIP + strip) * KSEL + lane] = li[j];
    }
}

// ---------------------------------------------------------------- kernel 3
__global__ void __launch_bounds__(256, 4)
knn_refine(const float* __restrict__ Qm, const float* __restrict__ X,
           const float* __restrict__ y, float* __restrict__ out,
           int q_total, int n) {
    __shared__ __align__(16) float qsm[8][DDIM];
    const int lane = threadIdx.x & 31;
    const int warp = threadIdx.x >> 5;
    const int q = blockIdx.x * 8 + warp;
    if (q >= q_total) return;

    reinterpret_cast<float4*>(qsm[warp])[lane] =
        reinterpret_cast<const float4*>(Qm + (size_t)q * DDIM)[lane];
    __syncwarp();
    const float4* q4 = reinterpret_cast<const float4*>(qsm[warp]);

    float ld = CUDART_INF_F;
    int   li = 0;
    const int* ip = g_idx + (size_t)q * NSTRIP * KSEL;

    #pragma unroll 1
    for (int g = 0; g < NSTRIP; g++) {
        int idx = ip[g * KSEL + lane];
        if (idx >= n) idx = n - 1;          // padded rows never selected; safety
        const float4* xr = reinterpret_cast<const float4*>(X + (size_t)idx * DDIM);
        float a0 = 0.f, a1 = 0.f, a2 = 0.f, a3 = 0.f;
        #pragma unroll 8
        for (int kk = 0; kk < 32; kk++) {
            float4 xv = xr[kk];
            float4 qv = q4[kk];
            a0 = fmaf(qv.x, xv.x, a0);
            a1 = fmaf(qv.y, xv.y, a1);
            a2 = fmaf(qv.z, xv.z, a2);
            a3 = fmaf(qv.w, xv.w, a3);
        }
        float val = fmaf(-2.f, (a0 + a1) + (a2 + a3), g_tsq[idx]);
        int   vi  = idx;
        float thr = __shfl_sync(0xffffffffu, ld, 31);
        unsigned pass = __ballot_sync(0xffffffffu, val < thr);
        while (pass) {
            int src = __ffs(pass) - 1;
            pass &= pass - 1;
            float v  = __shfl_sync(0xffffffffu, val, src);
            int   gi = __shfl_sync(0xffffffffu, vi,  src);
            unsigned m = __ballot_sync(0xffffffffu, v < ld);
            if (m) {
                int p = __ffs(m) - 1;
                float dn = __shfl_up_sync(0xffffffffu, ld, 1);
                int   in = __shfl_up_sync(0xffffffffu, li, 1);
                if (lane > p)       { ld = dn; li = in; }
                else if (lane == p) { ld = v;  li = gi; }
                thr = __shfl_sync(0xffffffffu, ld, 31);
            }
        }
    }

    float yv = y[li];
    #pragma unroll
    for (int o = 16; o; o >>= 1) yv += __shfl_xor_sync(0xffffffffu, yv, o);
    if (lane == 0) out[q] = yv * (1.0f / (float)KSEL);
}

// ---------------------------------------------------------------- launcher
extern "C" void kernel_launch(void* const* d_in, const int* in_sizes, int n_in,
                              void* d_out, int out_size) {
    const float* Qm = (const float*)d_in[0];
    const float* X  = (const float*)d_in[1];
    const float* y  = (const float*)d_in[2];
    const int q_total = in_sizes[0] / DDIM;   // 4096
    const int n       = in_sizes[2];          // 100000
    float* out = (float*)d_out;

    split_kernel<<<NPAD / 8, 256>>>(X, n);

    static int smem_set = 0;
    if (!smem_set) {
        cudaFuncSetAttribute(knn_main, cudaFuncAttributeMaxDynamicSharedMemorySize,
                             SM_TOTAL);
        smem_set = 1;
    }
    dim3 grid((q_total + QTILE - 1) / QTILE, SPLITS);
    knn_main<<<grid, NTHR, SM_TOTAL>>>(Qm, q_total);

    knn_refine<<<(q_total + 7) / 8, 256>>>(Qm, X, y, out, q_total, n);
}